// round 1
// baseline (speedup 1.0000x reference)
#include <cuda_runtime.h>
#include <cuda_bf16.h>

// CustomRotatedRoIAlign: fm (B=2, C=256, H=200, W=304) fp32, boxes (B, N=512, 5)
// out (B*N, C, 7, 7) fp32.
// One CTA per (b,n) box. Phase 1: 49 threads compute channel-invariant corner
// offsets + masked bilinear weights into SMEM. Phase 2: 256 threads sweep the
// C*49 outputs with coalesced stores; 4 gathers per output share a c*HW base.

#define RR_B 2
#define RR_C 256
#define RR_H 200
#define RR_W 304
#define RR_N 512
#define OUT_H 7
#define OUT_W 7
#define NPTS (OUT_H * OUT_W)
#define THREADS 256

__global__ __launch_bounds__(THREADS)
void rroi_align_kernel(const float* __restrict__ fm,
                       const float* __restrict__ boxes,
                       float* __restrict__ out)
{
    const int bn = blockIdx.x;           // 0 .. B*N-1
    const int b  = bn / RR_N;

    __shared__ int   s_off[4][NPTS];
    __shared__ float s_w[4][NPTS];

    const int tid = threadIdx.x;

    if (tid < NPTS) {
        const float* bx = boxes + (size_t)bn * 5;
        const float cx  = bx[0];
        const float cy  = bx[1];
        const float w   = bx[2];
        const float h   = bx[3];
        const float ang = bx[4];

        const float rad = -ang * (3.14159265358979323846f / 180.0f);
        float ss, cc;
        sincosf(rad, &ss, &cc);

        const float a00 =  (w / (float)RR_W) * cc;
        const float a01 = -(h / (float)RR_H) * ss;
        const float a02 =  2.0f * cx / (float)RR_W - 1.0f;
        const float a10 =  (w / (float)RR_W) * ss;
        const float a11 =  (h / (float)RR_H) * cc;
        const float a12 =  2.0f * cy / (float)RR_H - 1.0f;

        const int oy = tid / OUT_W;
        const int ox = tid - oy * OUT_W;
        const float xs = (2.0f * (float)ox + 1.0f) / (float)OUT_W - 1.0f;
        const float ys = (2.0f * (float)oy + 1.0f) / (float)OUT_H - 1.0f;

        const float gx = a00 * xs + a01 * ys + a02;
        const float gy = a10 * xs + a11 * ys + a12;

        const float ix = ((gx + 1.0f) * (float)RR_W - 1.0f) * 0.5f;
        const float iy = ((gy + 1.0f) * (float)RR_H - 1.0f) * 0.5f;

        const float x0 = floorf(ix);
        const float y0 = floorf(iy);
        const float wx1 = ix - x0;
        const float wy1 = iy - y0;

        #pragma unroll
        for (int k = 0; k < 4; k++) {
            const float xc = x0 + (float)(k & 1);
            const float yc = y0 + (float)(k >> 1);
            const float wgt = ((k & 1)  ? wx1 : (1.0f - wx1)) *
                              ((k >> 1) ? wy1 : (1.0f - wy1));
            const bool valid = (xc >= 0.0f) && (xc <= (float)(RR_W - 1)) &&
                               (yc >= 0.0f) && (yc <= (float)(RR_H - 1));
            const float xcl = fminf(fmaxf(xc, 0.0f), (float)(RR_W - 1));
            const float ycl = fminf(fmaxf(yc, 0.0f), (float)(RR_H - 1));
            const int xi = (int)xcl;
            const int yi = (int)ycl;
            s_off[k][tid] = yi * RR_W + xi;
            s_w[k][tid]   = valid ? wgt : 0.0f;
        }
    }
    __syncthreads();

    const size_t HW  = (size_t)RR_H * RR_W;
    const float* fmb = fm + (size_t)b * RR_C * HW;
    float* outb      = out + (size_t)bn * RR_C * NPTS;

    // 256 threads, C*49 = 12544 elements -> exactly 49 iterations/thread.
    #pragma unroll 4
    for (int idx = tid; idx < RR_C * NPTS; idx += THREADS) {
        const int c = idx / NPTS;
        const int p = idx - c * NPTS;
        const float* fc = fmb + (size_t)c * HW;
        const float v = s_w[0][p] * __ldg(fc + s_off[0][p])
                      + s_w[1][p] * __ldg(fc + s_off[1][p])
                      + s_w[2][p] * __ldg(fc + s_off[2][p])
                      + s_w[3][p] * __ldg(fc + s_off[3][p]);
        outb[idx] = v;
    }
}

extern "C" void kernel_launch(void* const* d_in, const int* in_sizes, int n_in,
                              void* d_out, int out_size)
{
    const float* fm    = (const float*)d_in[0];
    const float* boxes = (const float*)d_in[1];
    float* out         = (float*)d_out;

    rroi_align_kernel<<<RR_B * RR_N, THREADS>>>(fm, boxes, out);
}

// round 2
// speedup vs baseline: 1.3491x; 1.3491x over previous
#include <cuda_runtime.h>
#include <cuda_bf16.h>

// CustomRotatedRoIAlign via layout transform:
//   Pass 1: transpose fm (B,C,H,W) -> g_fm_t (B,H,W,C)  [channels contiguous]
//   Pass 2: one CTA per box; coalesced channel-vector gathers + SMEM-staged
//           coalesced writeout.

#define RR_B 2
#define RR_C 256
#define RR_H 200
#define RR_W 304
#define RR_HW (RR_H * RR_W)
#define RR_N 512
#define OUT_H 7
#define OUT_W 7
#define NPTS (OUT_H * OUT_W)

// 2*200*304*256 floats = 124.5 MB scratch (allowed: static __device__ array)
__device__ float g_fm_t[(size_t)RR_B * RR_HW * RR_C];

// ---------------------------------------------------------------------------
// Pass 1: tiled transpose (C, HW) -> (HW, C) per batch.
// HW = 60800 = 32*1900 exactly, C = 256 = 32*8 exactly -> no bounds checks.
// ---------------------------------------------------------------------------
__global__ __launch_bounds__(256)
void rroi_transpose_kernel(const float* __restrict__ fm)
{
    __shared__ float tile[32][33];

    const int b   = blockIdx.z;
    const int hw0 = blockIdx.x * 32;
    const int c0  = blockIdx.y * 32;
    const int tx  = threadIdx.x;   // 0..31
    const int ty  = threadIdx.y;   // 0..7

    const float* src = fm + ((size_t)b * RR_C + c0) * RR_HW + hw0;
    #pragma unroll
    for (int j = 0; j < 32; j += 8)
        tile[ty + j][tx] = src[(size_t)(ty + j) * RR_HW + tx];

    __syncthreads();

    float* dst = g_fm_t + ((size_t)b * RR_HW + hw0) * RR_C + c0;
    #pragma unroll
    for (int j = 0; j < 32; j += 8)
        dst[(size_t)(ty + j) * RR_C + tx] = tile[tx][ty + j];
}

// ---------------------------------------------------------------------------
// Pass 2: sampling. One CTA per (b,n). 256 threads = 256 channels.
// Dynamic SMEM: s_out[256*49] floats (50176 B) for coalesced writeout.
// ---------------------------------------------------------------------------
__global__ __launch_bounds__(256)
void rroi_sample_kernel(const float* __restrict__ boxes,
                        float* __restrict__ out)
{
    extern __shared__ float s_out[];          // RR_C * NPTS floats

    __shared__ int   s_off[4][NPTS];          // (y*W+x)*C offsets, channel-invariant
    __shared__ float s_w[4][NPTS];

    const int bn  = blockIdx.x;
    const int b   = bn / RR_N;
    const int tid = threadIdx.x;

    if (tid < NPTS) {
        const float* bx = boxes + (size_t)bn * 5;
        const float cx  = bx[0];
        const float cy  = bx[1];
        const float w   = bx[2];
        const float h   = bx[3];
        const float ang = bx[4];

        const float rad = -ang * (3.14159265358979323846f / 180.0f);
        float ss, cc;
        sincosf(rad, &ss, &cc);

        const float a00 =  (w / (float)RR_W) * cc;
        const float a01 = -(h / (float)RR_H) * ss;
        const float a02 =  2.0f * cx / (float)RR_W - 1.0f;
        const float a10 =  (w / (float)RR_W) * ss;
        const float a11 =  (h / (float)RR_H) * cc;
        const float a12 =  2.0f * cy / (float)RR_H - 1.0f;

        const int oy = tid / OUT_W;
        const int ox = tid - oy * OUT_W;
        const float xs = (2.0f * (float)ox + 1.0f) / (float)OUT_W - 1.0f;
        const float ys = (2.0f * (float)oy + 1.0f) / (float)OUT_H - 1.0f;

        const float gx = a00 * xs + a01 * ys + a02;
        const float gy = a10 * xs + a11 * ys + a12;

        const float ix = ((gx + 1.0f) * (float)RR_W - 1.0f) * 0.5f;
        const float iy = ((gy + 1.0f) * (float)RR_H - 1.0f) * 0.5f;

        const float x0 = floorf(ix);
        const float y0 = floorf(iy);
        const float wx1 = ix - x0;
        const float wy1 = iy - y0;

        #pragma unroll
        for (int k = 0; k < 4; k++) {
            const float xc = x0 + (float)(k & 1);
            const float yc = y0 + (float)(k >> 1);
            const float wgt = ((k & 1)  ? wx1 : (1.0f - wx1)) *
                              ((k >> 1) ? wy1 : (1.0f - wy1));
            const bool valid = (xc >= 0.0f) && (xc <= (float)(RR_W - 1)) &&
                               (yc >= 0.0f) && (yc <= (float)(RR_H - 1));
            const float xcl = fminf(fmaxf(xc, 0.0f), (float)(RR_W - 1));
            const float ycl = fminf(fmaxf(yc, 0.0f), (float)(RR_H - 1));
            const int xi = (int)xcl;
            const int yi = (int)ycl;
            s_off[k][tid] = (yi * RR_W + xi) * RR_C;
            s_w[k][tid]   = valid ? wgt : 0.0f;
        }
    }
    __syncthreads();

    const float* __restrict__ base = g_fm_t + (size_t)b * RR_HW * RR_C;
    const int c = tid;

    // All 8 warps walk the same p -> same 4x1KB corner vectors (L1 line reuse);
    // each warp's 32 lanes read 32 consecutive channels (128B coalesced).
    #pragma unroll 7
    for (int p = 0; p < NPTS; p++) {
        const float v = s_w[0][p] * __ldg(base + s_off[0][p] + c)
                      + s_w[1][p] * __ldg(base + s_off[1][p] + c)
                      + s_w[2][p] * __ldg(base + s_off[2][p] + c)
                      + s_w[3][p] * __ldg(base + s_off[3][p] + c);
        s_out[c * NPTS + p] = v;   // stride 49 (odd) -> bank-conflict-free
    }
    __syncthreads();

    // Coalesced writeout: 12544 floats = 3136 float4 per box.
    float4* __restrict__ dst = (float4*)(out + (size_t)bn * RR_C * NPTS);
    const float4* __restrict__ srcv = (const float4*)s_out;
    #pragma unroll
    for (int i = tid; i < (RR_C * NPTS) / 4; i += 256)
        dst[i] = srcv[i];
}

// ---------------------------------------------------------------------------

extern "C" void kernel_launch(void* const* d_in, const int* in_sizes, int n_in,
                              void* d_out, int out_size)
{
    const float* fm    = (const float*)d_in[0];
    const float* boxes = (const float*)d_in[1];
    float* out         = (float*)d_out;

    static int smem_set = 0;
    if (!smem_set) {
        cudaFuncSetAttribute(rroi_sample_kernel,
                             cudaFuncAttributeMaxDynamicSharedMemorySize,
                             RR_C * NPTS * (int)sizeof(float));
        smem_set = 1;
    }

    dim3 tgrid(RR_HW / 32, RR_C / 32, RR_B);
    dim3 tblock(32, 8);
    rroi_transpose_kernel<<<tgrid, tblock>>>(fm);

    rroi_sample_kernel<<<RR_B * RR_N, 256, RR_C * NPTS * (int)sizeof(float)>>>(boxes, out);
}

// round 3
// speedup vs baseline: 1.9305x; 1.4309x over previous
#include <cuda_runtime.h>
#include <cuda_bf16.h>

// CustomRotatedRoIAlign:
//   Pass 1: transpose fm (B,C,H,W) -> g_fm_t (B,H,W,C), float4 both sides.
//   Pass 2: one CTA (512 thr) per box; float4 channel-vector gathers,
//           SMEM-staged coalesced writeout.

#define RR_B 2
#define RR_C 256
#define RR_H 200
#define RR_W 304
#define RR_HW (RR_H * RR_W)
#define RR_N 512
#define OUT_H 7
#define OUT_W 7
#define NPTS (OUT_H * OUT_W)

// 2*60800*256 floats = 124.5 MB scratch
__device__ float g_fm_t[(size_t)RR_B * RR_HW * RR_C];

// ---------------------------------------------------------------------------
// Pass 1: transpose (C, HW) -> (HW, C). Tile: 32 channels x 128 hw.
// 256 threads; 4x LDG.128 + 4x STG.128 per thread; pitch-133 smem, both
// phases bank-conflict-free. HW = 60800 = 128*475, C = 256 = 32*8 (exact).
// ---------------------------------------------------------------------------
__global__ __launch_bounds__(256)
void rroi_transpose_kernel(const float* __restrict__ fm)
{
    __shared__ float tile[32][133];

    const int b   = blockIdx.z;
    const int c0  = blockIdx.y * 32;
    const int hw0 = blockIdx.x * 128;
    const int t   = threadIdx.x;

    // Load: thread (cl, h4) reads float4 along hw, 4 tiles of 32.
    const int cl = t >> 3;          // 0..31
    const int h4 = (t & 7) * 4;     // 0,4,...,28
    const float* src = fm + ((size_t)b * RR_C + c0) * RR_HW + hw0;

    #pragma unroll
    for (int j = 0; j < 4; j++) {
        const float4 v = *(const float4*)(src + (size_t)cl * RR_HW + h4 + 32 * j);
        float* tp = &tile[cl][h4 + 32 * j];
        tp[0] = v.x; tp[1] = v.y; tp[2] = v.z; tp[3] = v.w;
    }
    __syncthreads();

    // Store: thread (hwr, c4) writes float4 along channels.
    const int c4  = (t & 7) * 4;    // 0,4,...,28
    const int hwr = t >> 3;         // 0..31
    float* dst = g_fm_t + ((size_t)b * RR_HW + hw0) * RR_C + c0;

    #pragma unroll
    for (int j = 0; j < 4; j++) {
        const int hw = hwr + 32 * j;
        float4 v;
        v.x = tile[c4 + 0][hw];
        v.y = tile[c4 + 1][hw];
        v.z = tile[c4 + 2][hw];
        v.w = tile[c4 + 3][hw];
        *(float4*)(dst + (size_t)hw * RR_C + c4) = v;
    }
}

// ---------------------------------------------------------------------------
// Pass 2: sampling. One CTA per (b,n), 512 threads.
// Thread = (channel-group of 4, point-group of 8). 7 iterations, 4 independent
// LDG.128 each. Dynamic SMEM s_out[256*49] for the coalesced writeout.
// ---------------------------------------------------------------------------
__global__ __launch_bounds__(512)
void rroi_sample_kernel(const float* __restrict__ boxes,
                        float* __restrict__ out)
{
    extern __shared__ float s_out[];      // RR_C * NPTS floats

    __shared__ int   s_off[4][NPTS];      // (y*W+x)*C float-offsets
    __shared__ float s_w[4][NPTS];

    const int bn  = blockIdx.x;
    const int b   = bn / RR_N;
    const int tid = threadIdx.x;

    if (tid < NPTS) {
        const float* bx = boxes + (size_t)bn * 5;
        const float cx  = bx[0];
        const float cy  = bx[1];
        const float w   = bx[2];
        const float h   = bx[3];
        const float ang = bx[4];

        const float rad = -ang * (3.14159265358979323846f / 180.0f);
        float ss, cc;
        sincosf(rad, &ss, &cc);

        const float a00 =  (w / (float)RR_W) * cc;
        const float a01 = -(h / (float)RR_H) * ss;
        const float a02 =  2.0f * cx / (float)RR_W - 1.0f;
        const float a10 =  (w / (float)RR_W) * ss;
        const float a11 =  (h / (float)RR_H) * cc;
        const float a12 =  2.0f * cy / (float)RR_H - 1.0f;

        const int oy = tid / OUT_W;
        const int ox = tid - oy * OUT_W;
        const float xs = (2.0f * (float)ox + 1.0f) / (float)OUT_W - 1.0f;
        const float ys = (2.0f * (float)oy + 1.0f) / (float)OUT_H - 1.0f;

        const float gx = a00 * xs + a01 * ys + a02;
        const float gy = a10 * xs + a11 * ys + a12;

        const float ix = ((gx + 1.0f) * (float)RR_W - 1.0f) * 0.5f;
        const float iy = ((gy + 1.0f) * (float)RR_H - 1.0f) * 0.5f;

        const float x0 = floorf(ix);
        const float y0 = floorf(iy);
        const float wx1 = ix - x0;
        const float wy1 = iy - y0;

        #pragma unroll
        for (int k = 0; k < 4; k++) {
            const float xc = x0 + (float)(k & 1);
            const float yc = y0 + (float)(k >> 1);
            const float wgt = ((k & 1)  ? wx1 : (1.0f - wx1)) *
                              ((k >> 1) ? wy1 : (1.0f - wy1));
            const bool valid = (xc >= 0.0f) && (xc <= (float)(RR_W - 1)) &&
                               (yc >= 0.0f) && (yc <= (float)(RR_H - 1));
            const float xcl = fminf(fmaxf(xc, 0.0f), (float)(RR_W - 1));
            const float ycl = fminf(fmaxf(yc, 0.0f), (float)(RR_H - 1));
            const int xi = (int)xcl;
            const int yi = (int)ycl;
            s_off[k][tid] = (yi * RR_W + xi) * RR_C;
            s_w[k][tid]   = valid ? wgt : 0.0f;
        }
    }
    __syncthreads();

    const int cg = tid & 63;              // channel group (4 channels)
    const int pg = tid >> 6;              // 0..7 point group
    const float* __restrict__ base =
        g_fm_t + (size_t)b * RR_HW * RR_C + 4 * cg;

    #pragma unroll
    for (int j = 0; j < 7; j++) {
        const int p = j * 8 + pg;
        if (p < NPTS) {                   // only j==6 is partial
            const float4 v0 = *(const float4*)(base + s_off[0][p]);
            const float4 v1 = *(const float4*)(base + s_off[1][p]);
            const float4 v2 = *(const float4*)(base + s_off[2][p]);
            const float4 v3 = *(const float4*)(base + s_off[3][p]);
            const float w0 = s_w[0][p], w1 = s_w[1][p];
            const float w2 = s_w[2][p], w3 = s_w[3][p];
            float4 r;
            r.x = w0 * v0.x + w1 * v1.x + w2 * v2.x + w3 * v3.x;
            r.y = w0 * v0.y + w1 * v1.y + w2 * v2.y + w3 * v3.y;
            r.z = w0 * v0.z + w1 * v1.z + w2 * v2.z + w3 * v3.z;
            r.w = w0 * v0.w + w1 * v1.w + w2 * v2.w + w3 * v3.w;
            float* o = s_out + (4 * cg) * NPTS + p;
            o[0 * NPTS] = r.x;
            o[1 * NPTS] = r.y;
            o[2 * NPTS] = r.z;
            o[3 * NPTS] = r.w;
        }
    }
    __syncthreads();

    // Coalesced writeout: 12544 floats = 3136 float4 per box.
    float4* __restrict__ dst = (float4*)(out + (size_t)bn * RR_C * NPTS);
    const float4* __restrict__ srcv = (const float4*)s_out;
    #pragma unroll
    for (int i = tid; i < (RR_C * NPTS) / 4; i += 512)
        dst[i] = srcv[i];
}

// ---------------------------------------------------------------------------

extern "C" void kernel_launch(void* const* d_in, const int* in_sizes, int n_in,
                              void* d_out, int out_size)
{
    const float* fm    = (const float*)d_in[0];
    const float* boxes = (const float*)d_in[1];
    float* out         = (float*)d_out;

    static int smem_set = 0;
    if (!smem_set) {
        cudaFuncSetAttribute(rroi_sample_kernel,
                             cudaFuncAttributeMaxDynamicSharedMemorySize,
                             RR_C * NPTS * (int)sizeof(float));
        smem_set = 1;
    }

    dim3 tgrid(RR_HW / 128, RR_C / 32, RR_B);
    rroi_transpose_kernel<<<tgrid, 256>>>(fm);

    rroi_sample_kernel<<<RR_B * RR_N, 512, RR_C * NPTS * (int)sizeof(float)>>>(boxes, out);
}

// round 4
// speedup vs baseline: 2.6171x; 1.3556x over previous
#include <cuda_runtime.h>
#include <cuda_fp16.h>
#include <cuda_bf16.h>

// CustomRotatedRoIAlign:
//   Pass 1: transpose fm (B,C,H,W) fp32 -> g_fm_h (B,H,W,C) fp16.
//   Pass 2: one CTA (512 thr) per box; fp16 channel-vector gathers (fp32
//           accumulation), SMEM-staged coalesced writeout.

#define RR_B 2
#define RR_C 256
#define RR_H 200
#define RR_W 304
#define RR_HW (RR_H * RR_W)
#define RR_N 512
#define OUT_H 7
#define OUT_W 7
#define NPTS (OUT_H * OUT_W)

// 2*60800*256 halves = 62.3 MB scratch
__device__ __half g_fm_h[(size_t)RR_B * RR_HW * RR_C];

// ---------------------------------------------------------------------------
// Pass 1: transpose (C, HW) fp32 -> (HW, C) fp16. Tile: 32 c x 128 hw.
// 256 threads; 4x LDG.128 in, 4x STG.64 (4 halves) out; pitch-133 smem keeps
// both phases bank-conflict-free. HW = 128*475, C = 32*8 exact.
// ---------------------------------------------------------------------------
__global__ __launch_bounds__(256)
void rroi_transpose_kernel(const float* __restrict__ fm)
{
    __shared__ float tile[32][133];

    const int b   = blockIdx.z;
    const int c0  = blockIdx.y * 32;
    const int hw0 = blockIdx.x * 128;
    const int t   = threadIdx.x;

    // Load: thread (cl, h4) reads float4 along hw, 4 chunks of 32.
    const int cl = t >> 3;          // 0..31
    const int h4 = (t & 7) * 4;     // 0,4,...,28
    const float* src = fm + ((size_t)b * RR_C + c0) * RR_HW + hw0;

    #pragma unroll
    for (int j = 0; j < 4; j++) {
        const float4 v = *(const float4*)(src + (size_t)cl * RR_HW + h4 + 32 * j);
        float* tp = &tile[cl][h4 + 32 * j];
        tp[0] = v.x; tp[1] = v.y; tp[2] = v.z; tp[3] = v.w;
    }
    __syncthreads();

    // Store: thread (hwr, c4) writes 4 halves along channels.
    const int c4  = (t & 7) * 4;    // 0,4,...,28
    const int hwr = t >> 3;         // 0..31
    __half* dst = g_fm_h + ((size_t)(b * RR_HW + hw0)) * RR_C + c0;

    #pragma unroll
    for (int j = 0; j < 4; j++) {
        const int hw = hwr + 32 * j;
        const __half2 lo = __floats2half2_rn(tile[c4 + 0][hw], tile[c4 + 1][hw]);
        const __half2 hi = __floats2half2_rn(tile[c4 + 2][hw], tile[c4 + 3][hw]);
        uint2 pk;
        pk.x = *(const unsigned int*)&lo;
        pk.y = *(const unsigned int*)&hi;
        *(uint2*)(dst + (size_t)hw * RR_C + c4) = pk;
    }
}

// ---------------------------------------------------------------------------
// Pass 2: sampling. One CTA per (b,n), 512 threads.
// Thread = (channel-group of 4, point-group of 8). 7 iterations, 4 independent
// 8B gathers each (fp16), fp32 accumulate. Dynamic SMEM s_out[256*49].
// ---------------------------------------------------------------------------
__global__ __launch_bounds__(512)
void rroi_sample_kernel(const float* __restrict__ boxes,
                        float* __restrict__ out)
{
    extern __shared__ float s_out[];      // RR_C * NPTS floats

    __shared__ int   s_off[4][NPTS];      // (y*W+x)*C half-offsets
    __shared__ float s_w[4][NPTS];

    const int bn  = blockIdx.x;
    const int b   = bn / RR_N;
    const int tid = threadIdx.x;

    if (tid < NPTS) {
        const float* bx = boxes + (size_t)bn * 5;
        const float cx  = bx[0];
        const float cy  = bx[1];
        const float w   = bx[2];
        const float h   = bx[3];
        const float ang = bx[4];

        const float rad = -ang * (3.14159265358979323846f / 180.0f);
        float ss, cc;
        sincosf(rad, &ss, &cc);

        const float a00 =  (w / (float)RR_W) * cc;
        const float a01 = -(h / (float)RR_H) * ss;
        const float a02 =  2.0f * cx / (float)RR_W - 1.0f;
        const float a10 =  (w / (float)RR_W) * ss;
        const float a11 =  (h / (float)RR_H) * cc;
        const float a12 =  2.0f * cy / (float)RR_H - 1.0f;

        const int oy = tid / OUT_W;
        const int ox = tid - oy * OUT_W;
        const float xs = (2.0f * (float)ox + 1.0f) / (float)OUT_W - 1.0f;
        const float ys = (2.0f * (float)oy + 1.0f) / (float)OUT_H - 1.0f;

        const float gx = a00 * xs + a01 * ys + a02;
        const float gy = a10 * xs + a11 * ys + a12;

        const float ix = ((gx + 1.0f) * (float)RR_W - 1.0f) * 0.5f;
        const float iy = ((gy + 1.0f) * (float)RR_H - 1.0f) * 0.5f;

        const float x0 = floorf(ix);
        const float y0 = floorf(iy);
        const float wx1 = ix - x0;
        const float wy1 = iy - y0;

        #pragma unroll
        for (int k = 0; k < 4; k++) {
            const float xc = x0 + (float)(k & 1);
            const float yc = y0 + (float)(k >> 1);
            const float wgt = ((k & 1)  ? wx1 : (1.0f - wx1)) *
                              ((k >> 1) ? wy1 : (1.0f - wy1));
            const bool valid = (xc >= 0.0f) && (xc <= (float)(RR_W - 1)) &&
                               (yc >= 0.0f) && (yc <= (float)(RR_H - 1));
            const float xcl = fminf(fmaxf(xc, 0.0f), (float)(RR_W - 1));
            const float ycl = fminf(fmaxf(yc, 0.0f), (float)(RR_H - 1));
            const int xi = (int)xcl;
            const int yi = (int)ycl;
            s_off[k][tid] = (yi * RR_W + xi) * RR_C;
            s_w[k][tid]   = valid ? wgt : 0.0f;
        }
    }
    __syncthreads();

    const int cg = tid & 63;              // channel group (4 channels)
    const int pg = tid >> 6;              // 0..7 point group
    const __half* __restrict__ base =
        g_fm_h + (size_t)b * RR_HW * RR_C + 4 * cg;

    #pragma unroll
    for (int j = 0; j < 7; j++) {
        const int p = j * 8 + pg;
        if (p < NPTS) {                   // only j==6 is partial
            const uint2 u0 = *(const uint2*)(base + s_off[0][p]);
            const uint2 u1 = *(const uint2*)(base + s_off[1][p]);
            const uint2 u2 = *(const uint2*)(base + s_off[2][p]);
            const uint2 u3 = *(const uint2*)(base + s_off[3][p]);
            const float w0 = s_w[0][p], w1 = s_w[1][p];
            const float w2 = s_w[2][p], w3 = s_w[3][p];

            const float2 a0 = __half22float2(*(const __half2*)&u0.x);
            const float2 b0 = __half22float2(*(const __half2*)&u0.y);
            const float2 a1 = __half22float2(*(const __half2*)&u1.x);
            const float2 b1 = __half22float2(*(const __half2*)&u1.y);
            const float2 a2 = __half22float2(*(const __half2*)&u2.x);
            const float2 b2 = __half22float2(*(const __half2*)&u2.y);
            const float2 a3 = __half22float2(*(const __half2*)&u3.x);
            const float2 b3 = __half22float2(*(const __half2*)&u3.y);

            float4 r;
            r.x = w0 * a0.x + w1 * a1.x + w2 * a2.x + w3 * a3.x;
            r.y = w0 * a0.y + w1 * a1.y + w2 * a2.y + w3 * a3.y;
            r.z = w0 * b0.x + w1 * b1.x + w2 * b2.x + w3 * b3.x;
            r.w = w0 * b0.y + w1 * b1.y + w2 * b2.y + w3 * b3.y;

            float* o = s_out + (4 * cg) * NPTS + p;
            o[0 * NPTS] = r.x;
            o[1 * NPTS] = r.y;
            o[2 * NPTS] = r.z;
            o[3 * NPTS] = r.w;
        }
    }
    __syncthreads();

    // Coalesced writeout: 12544 floats = 3136 float4 per box.
    float4* __restrict__ dst = (float4*)(out + (size_t)bn * RR_C * NPTS);
    const float4* __restrict__ srcv = (const float4*)s_out;
    #pragma unroll
    for (int i = tid; i < (RR_C * NPTS) / 4; i += 512)
        dst[i] = srcv[i];
}

// ---------------------------------------------------------------------------

extern "C" void kernel_launch(void* const* d_in, const int* in_sizes, int n_in,
                              void* d_out, int out_size)
{
    const float* fm    = (const float*)d_in[0];
    const float* boxes = (const float*)d_in[1];
    float* out         = (float*)d_out;

    static int smem_set = 0;
    if (!smem_set) {
        cudaFuncSetAttribute(rroi_sample_kernel,
                             cudaFuncAttributeMaxDynamicSharedMemorySize,
                             RR_C * NPTS * (int)sizeof(float));
        smem_set = 1;
    }

    dim3 tgrid(RR_HW / 128, RR_C / 32, RR_B);
    rroi_transpose_kernel<<<tgrid, 256>>>(fm);

    rroi_sample_kernel<<<RR_B * RR_N, 512, RR_C * NPTS * (int)sizeof(float)>>>(boxes, out);
}